// round 3
// baseline (speedup 1.0000x reference)
#include <cuda_runtime.h>
#include <cstdint>

// Problem constants
#define HW 16384          // 128*128
#define NB 4              // x batches
#define NG 4              // groups
#define CG 16             // channels per group
#define K2 9

// Scratch (allocation-free: __device__ globals)
__device__ __align__(16) float g_z[NB * 80 * HW];          // 5 convs x 16ch
__device__ __align__(16) float g_off[NB * NG * 18 * HW];   // per-group offsets
__device__ __align__(16) float g_mask[NB * K2 * HW];       // sigmoided mask

// ---------------------------------------------------------------------------
// Kernel 1: five 3x3 convs (16->16 ch, pad 1) on x[:, :16].
// grid (8, 8, NB*5), block 256.  Tile 16x16; thread = (oc-group of 4, pixel
// quad of 4 along w).  Weights + input tile staged in smem.
// ---------------------------------------------------------------------------
__global__ __launch_bounds__(256) void conv3x3_kernel(
    const float* __restrict__ x,
    const float* __restrict__ mask_pw,   // (16,16,3,3)
    const float* __restrict__ off_pw)    // (4,16,16,3,3)
{
    __shared__ float s_in[16 * 18 * 18];   // [ic][18][18]
    __shared__ float s_w[16 * 16 * 9];     // [oc][ic][9]

    const int bz = blockIdx.z;
    const int j  = bz % 5;        // 0 = mask conv, 1..4 = offset conv g
    const int b  = bz / 5;
    const int h0 = blockIdx.y * 16;
    const int w0 = blockIdx.x * 16;
    const int tid = threadIdx.x;

    const float* xb = x + (size_t)b * 64 * HW;
    for (int idx = tid; idx < 16 * 18 * 18; idx += 256) {
        int ic  = idx / 324;
        int rem = idx - ic * 324;
        int ly  = rem / 18;
        int lx  = rem - ly * 18;
        int gy = h0 - 1 + ly;
        int gx = w0 - 1 + lx;
        float v = 0.f;
        if ((unsigned)gy < 128u && (unsigned)gx < 128u)
            v = xb[ic * HW + gy * 128 + gx];
        s_in[idx] = v;
    }
    const float* wsrc = (j == 0) ? mask_pw : (off_pw + (j - 1) * 2304);
    for (int idx = tid; idx < 2304; idx += 256) s_w[idx] = wsrc[idx];
    __syncthreads();

    const int og  = tid >> 6;        // oc group 0..3 -> oc = og*4 .. og*4+3
    const int pix = tid & 63;
    const int r   = pix >> 2;        // row in tile 0..15
    const int c0  = (pix & 3) * 4;   // col base 0,4,8,12

    float acc[4][4];
#pragma unroll
    for (int oc = 0; oc < 4; oc++)
#pragma unroll
        for (int p = 0; p < 4; p++) acc[oc][p] = 0.f;

#pragma unroll 1
    for (int ic = 0; ic < 16; ic++) {
        float v[18];
        const float* sp = s_in + ic * 324 + r * 18 + c0;
#pragma unroll
        for (int dy = 0; dy < 3; dy++)
#pragma unroll
            for (int dx = 0; dx < 6; dx++)
                v[dy * 6 + dx] = sp[dy * 18 + dx];

        const float* wp = s_w + (og * 4) * 144 + ic * 9;
#pragma unroll
        for (int oc = 0; oc < 4; oc++) {
#pragma unroll
            for (int t = 0; t < 9; t++) {
                float wv = wp[oc * 144 + t];
                int dy = t / 3, dx = t % 3;
#pragma unroll
                for (int p = 0; p < 4; p++)
                    acc[oc][p] = fmaf(wv, v[dy * 6 + dx + p], acc[oc][p]);
            }
        }
    }

    const int ho = h0 + r;
    float* zp = g_z + ((size_t)(b * 80 + j * 16 + og * 4)) * HW + ho * 128 + w0 + c0;
#pragma unroll
    for (int oc = 0; oc < 4; oc++) {
        float4 o = make_float4(acc[oc][0], acc[oc][1], acc[oc][2], acc[oc][3]);
        *reinterpret_cast<float4*>(zp + (size_t)oc * HW) = o;
    }
}

// ---------------------------------------------------------------------------
// Kernel 2: 1x1 heads.  out[o] = W[o,0:16] . z_head + W[o,16:64] . x[16:64] + b
// MASK head (NO=9) applies sigmoid -> g_mask.  Offset heads (NO=18) -> g_off.
// Each thread handles 2 pixels (float2).
// ---------------------------------------------------------------------------
template <int NO, bool MASK>
__global__ __launch_bounds__(128) void head_kernel(
    const float* __restrict__ x,
    const float* __restrict__ wmat,
    const float* __restrict__ bias)
{
    __shared__ float s_w[NO * 64];

    const int slice = blockIdx.y;            // MASK: b;  else b*4+g
    const int b = MASK ? slice : (slice >> 2);
    const int m = MASK ? 0 : ((slice & 3) + 1);   // conv-head index in g_z
    const float* wsrc = MASK ? wmat : (wmat + (slice & 3) * NO * 64);
    for (int i = threadIdx.x; i < NO * 64; i += 128) s_w[i] = wsrc[i];
    __syncthreads();

    const int px2 = blockIdx.x * 128 + threadIdx.x;
    const int px  = px2 * 2;

    float2 acc[NO];
#pragma unroll
    for (int o = 0; o < NO; o++) acc[o] = make_float2(0.f, 0.f);

    const float* zb = g_z + (size_t)(b * 80 + m * 16) * HW + px;
    const float* xb = x   + (size_t)(b * 64 + 16)     * HW + px;

#pragma unroll 8
    for (int c = 0; c < 16; c++) {
        float2 v = *reinterpret_cast<const float2*>(zb + (size_t)c * HW);
#pragma unroll
        for (int o = 0; o < NO; o++) {
            float wv = s_w[o * 64 + c];
            acc[o].x = fmaf(wv, v.x, acc[o].x);
            acc[o].y = fmaf(wv, v.y, acc[o].y);
        }
    }
#pragma unroll 8
    for (int c = 0; c < 48; c++) {
        float2 v = *reinterpret_cast<const float2*>(xb + (size_t)c * HW);
#pragma unroll
        for (int o = 0; o < NO; o++) {
            float wv = s_w[o * 64 + 16 + c];
            acc[o].x = fmaf(wv, v.x, acc[o].x);
            acc[o].y = fmaf(wv, v.y, acc[o].y);
        }
    }

    if (MASK) {
        float* mp = g_mask + (size_t)b * 9 * HW + px;
#pragma unroll
        for (int o = 0; o < NO; o++) {
            float bb = bias[o];
            float sx = 1.f / (1.f + __expf(-(acc[o].x + bb)));
            float sy = 1.f / (1.f + __expf(-(acc[o].y + bb)));
            *reinterpret_cast<float2*>(mp + (size_t)o * HW) = make_float2(sx, sy);
        }
    } else {
        float* op = g_off + (size_t)slice * 18 * HW + px;
        const float* bs = bias + (slice & 3) * 18;
#pragma unroll
        for (int o = 0; o < NO; o++) {
            float bb = bs[o];
            *reinterpret_cast<float2*>(op + (size_t)o * HW) =
                make_float2(acc[o].x + bb, acc[o].y + bb);
        }
    }
}

// ---------------------------------------------------------------------------
// Kernel 3: modulated deformable bilinear sampling.
// One block per (b, g, h) row: 2048 blocks x 256 threads.
// Phase 1: 9 taps x 128 px corner indices+weights -> smem (coalesced off/mask).
// Phase 2: thread = (channel-group of 4, pixel-pair); gathers 4 corners x
//          2 images x 4 channels per tap; stores float2 per (c,k).
// ---------------------------------------------------------------------------
__global__ __launch_bounds__(256) void sample_kernel(
    const float* __restrict__ y, float* __restrict__ out)
{
    __shared__ int   s_ci[9][128][4];
    __shared__ float s_cw[9][128][4];

    int bz = blockIdx.x;
    const int h = bz & 127;  bz >>= 7;
    const int g = bz & 3;
    const int b = bz >> 2;

    const float* off = g_off + ((size_t)(b * 4 + g) * 18) * HW + h * 128;
    const float* msk = g_mask + (size_t)b * 9 * HW + h * 128;
    const int dil = 2 * g + 1;

    // Phase 1: corner data for all 9 taps x 128 pixels of this row.
    for (int t = threadIdx.x; t < 9 * 64; t += 256) {
        const int k  = t / 64;
        const int w2 = t - k * 64;
        const int w  = w2 * 2;
        const int ky = k / 3 - 1;
        const int kx = k % 3 - 1;
        const float basey = (float)(h + ky * dil);
        const float basex = (float)(w + kx * dil);

#pragma unroll
        for (int p = 0; p < 2; p++) {
            float py  = basey + off[(2 * k) * HW + w + p];
            float pxx = basex + (float)p + off[(2 * k + 1) * HW + w + p];
            float m   = msk[k * HW + w + p];

            float fy0 = floorf(py);
            float fx0 = floorf(pxx);
            float wy = py - fy0;
            float wx = pxx - fx0;

            bool vy0 = (fy0 >= 0.f)  && (fy0 <= 127.f);
            bool vy1 = (fy0 >= -1.f) && (fy0 <= 126.f);
            bool vx0 = (fx0 >= 0.f)  && (fx0 <= 127.f);
            bool vx1 = (fx0 >= -1.f) && (fx0 <= 126.f);

            int y0c = (int)fminf(fmaxf(fy0,       0.f), 127.f);
            int y1c = (int)fminf(fmaxf(fy0 + 1.f, 0.f), 127.f);
            int x0c = (int)fminf(fmaxf(fx0,       0.f), 127.f);
            int x1c = (int)fminf(fmaxf(fx0 + 1.f, 0.f), 127.f);

            float w00 = (1.f - wy) * (1.f - wx) * m; if (!(vy0 && vx0)) w00 = 0.f;
            float w01 = (1.f - wy) * wx        * m; if (!(vy0 && vx1)) w01 = 0.f;
            float w10 = wy        * (1.f - wx) * m; if (!(vy1 && vx0)) w10 = 0.f;
            float w11 = wy        * wx         * m; if (!(vy1 && vx1)) w11 = 0.f;

            s_ci[k][w + p][0] = y0c * 128 + x0c;  s_cw[k][w + p][0] = w00;
            s_ci[k][w + p][1] = y0c * 128 + x1c;  s_cw[k][w + p][1] = w01;
            s_ci[k][w + p][2] = y1c * 128 + x0c;  s_cw[k][w + p][2] = w10;
            s_ci[k][w + p][3] = y1c * 128 + x1c;  s_cw[k][w + p][3] = w11;
        }
    }
    __syncthreads();

    // Phase 2: gathers.
    const int c4 = threadIdx.x >> 6;       // channel group 0..3
    const int w2 = threadIdx.x & 63;
    const int w  = w2 * 2;
    const int c0 = c4 * 4;

    const float* y1 = y + (size_t)(b * 64 + g * 16 + c0) * HW;
    const float* y2 = y + (size_t)((b + 4) * 64 + g * 16 + c0) * HW;
    float* o1 = out + ((size_t)(b * 64 + g * 16 + c0) * 9) * HW + h * 128 + w;
    float* o2 = out + ((size_t)((b + 4) * 64 + g * 16 + c0) * 9) * HW + h * 128 + w;

#pragma unroll 1
    for (int k = 0; k < 9; k++) {
        const int4   ci0 = *reinterpret_cast<const int4*>(&s_ci[k][w][0]);
        const int4   ci1 = *reinterpret_cast<const int4*>(&s_ci[k][w + 1][0]);
        const float4 cw0 = *reinterpret_cast<const float4*>(&s_cw[k][w][0]);
        const float4 cw1 = *reinterpret_cast<const float4*>(&s_cw[k][w + 1][0]);

#pragma unroll
        for (int c = 0; c < 4; c++) {
            const float* s1 = y1 + (size_t)c * HW;
            const float* s2 = y2 + (size_t)c * HW;

            float r1x = cw0.x * s1[ci0.x] + cw0.y * s1[ci0.y]
                      + cw0.z * s1[ci0.z] + cw0.w * s1[ci0.w];
            float r1y = cw1.x * s1[ci1.x] + cw1.y * s1[ci1.y]
                      + cw1.z * s1[ci1.z] + cw1.w * s1[ci1.w];
            float r2x = cw0.x * s2[ci0.x] + cw0.y * s2[ci0.y]
                      + cw0.z * s2[ci0.z] + cw0.w * s2[ci0.w];
            float r2y = cw1.x * s2[ci1.x] + cw1.y * s2[ci1.y]
                      + cw1.z * s2[ci1.z] + cw1.w * s2[ci1.w];

            *reinterpret_cast<float2*>(o1 + (size_t)(c * 9 + k) * HW) = make_float2(r1x, r1y);
            *reinterpret_cast<float2*>(o2 + (size_t)(c * 9 + k) * HW) = make_float2(r2x, r2y);
        }
    }
}

// ---------------------------------------------------------------------------
extern "C" void kernel_launch(void* const* d_in, const int* in_sizes, int n_in,
                              void* d_out, int out_size)
{
    // Defensive remap by element count (all sizes unique)
    const float *x = nullptr, *y = nullptr, *off_pw = nullptr, *off_w = nullptr,
                *off_b = nullptr, *mask_pw = nullptr, *mask_w = nullptr, *mask_b = nullptr;
    for (int i = 0; i < n_in; i++) {
        switch (in_sizes[i]) {
            case 4194304: x       = (const float*)d_in[i]; break;
            case 8388608: y       = (const float*)d_in[i]; break;
            case 9216:    off_pw  = (const float*)d_in[i]; break;
            case 4608:    off_w   = (const float*)d_in[i]; break;
            case 72:      off_b   = (const float*)d_in[i]; break;
            case 2304:    mask_pw = (const float*)d_in[i]; break;
            case 576:     mask_w  = (const float*)d_in[i]; break;
            case 9:       mask_b  = (const float*)d_in[i]; break;
            default: break;
        }
    }
    float* out = (float*)d_out;

    conv3x3_kernel<<<dim3(8, 8, NB * 5), 256>>>(x, mask_pw, off_pw);
    head_kernel<9,  true ><<<dim3(64, NB),      128>>>(x, mask_w, mask_b);
    head_kernel<18, false><<<dim3(64, NB * NG), 128>>>(x, off_w, off_b);
    sample_kernel<<<NB * NG * 128, 256>>>(y, out);
}

// round 4
// speedup vs baseline: 1.3357x; 1.3357x over previous
#include <cuda_runtime.h>
#include <cstdint>

#define HW 16384          // 128*128
#define NB 4
#define NG 4
#define K2 9

// Scratch (allocation-free __device__ globals)
__device__ __align__(16) float g_off[NB * NG * K2 * HW * 2];  // [slice][k][px][(dy,dx)]
__device__ __align__(16) float g_mask[NB * K2 * HW];          // [b][k][px]
__device__ __align__(16) float g_wf[5 * 18 * 16 * 9];         // folded 3x3 weights [j][o][ic][t]
__device__ __align__(16) float g_w1[5 * 18 * 48];             // 1x1 remainder [j][o][c]

// ---------------------------------------------------------------------------
// Fold kernel: g_wf[j][o][ic][t] = sum_c headW[j][o][c] * convW[j][c][ic][t]
//              g_w1[j][o][c]     = headW[j][o][16+c]
// j=0: mask head (NO=9), j=1..4: offset head g=j-1 (NO=18)
// ---------------------------------------------------------------------------
__global__ void fold_kernel(
    const float* __restrict__ mask_pw,  // (16,16,3,3)
    const float* __restrict__ mask_w,   // (9,64)
    const float* __restrict__ off_pw,   // (4,16,16,3,3)
    const float* __restrict__ off_w)    // (4,18,64)
{
    int idx = blockIdx.x * 256 + threadIdx.x;
    // folded 3x3 part: 5 * 18 * 144 entries (j=0 uses only o<9)
    for (int e = idx; e < 5 * 18 * 144; e += gridDim.x * 256) {
        int j  = e / (18 * 144);
        int r  = e - j * 18 * 144;
        int o  = r / 144;
        int it = r - o * 144;           // ic*9 + t
        if (j == 0 && o >= 9) { g_wf[e] = 0.f; continue; }
        const float* hw = (j == 0) ? (mask_w + o * 64)
                                   : (off_w + ((j - 1) * 18 + o) * 64);
        const float* cw = (j == 0) ? (mask_pw + it)
                                   : (off_pw + (j - 1) * 2304 + it);
        float s = 0.f;
#pragma unroll
        for (int c = 0; c < 16; c++)
            s = fmaf(hw[c], cw[c * 144], s);
        g_wf[e] = s;
    }
    // 1x1 remainder: 5 * 18 * 48
    for (int e = idx; e < 5 * 18 * 48; e += gridDim.x * 256) {
        int j = e / (18 * 48);
        int r = e - j * 18 * 48;
        int o = r / 48;
        int c = r - o * 48;
        if (j == 0 && o >= 9) { g_w1[e] = 0.f; continue; }
        const float* hw = (j == 0) ? (mask_w + o * 64)
                                   : (off_w + ((j - 1) * 18 + o) * 64);
        g_w1[e] = hw[16 + c];
    }
}

// ---------------------------------------------------------------------------
// Stage A: fused (3x3 conv 16->NO) + (1x1 48->NO) + bias.
// NO=18: offsets for group g=j-1, stored interleaved (dy,dx) per pixel.
// NO=9 : mask with sigmoid.
// grid (8,8, NB * nheads), block 64.  Tile 16x16, 4 px/thread, all NO outputs.
// ---------------------------------------------------------------------------
template <int NO>
__global__ __launch_bounds__(64) void fused_head_kernel(
    const float* __restrict__ x,
    const float* __restrict__ mask_b,   // (9,)
    const float* __restrict__ off_b)    // (4,18)
{
    __shared__ float s_in[16 * 18 * 18];
    __shared__ float s_wf[NO * 144];
    __shared__ float s_w1[NO * 48];

    const int bz = blockIdx.z;
    const int nh = (NO == 9) ? 1 : 4;
    const int hj = bz % nh;                   // head index within kind
    const int b  = bz / nh;
    const int j  = (NO == 9) ? 0 : (hj + 1);  // global head id
    const int h0 = blockIdx.y * 16;
    const int w0 = blockIdx.x * 16;
    const int tid = threadIdx.x;

    const float* xb = x + (size_t)b * 64 * HW;
    for (int idx = tid; idx < 16 * 18 * 18; idx += 64) {
        int ic  = idx / 324;
        int rem = idx - ic * 324;
        int ly  = rem / 18;
        int lx  = rem - ly * 18;
        int gy = h0 - 1 + ly;
        int gx = w0 - 1 + lx;
        float v = 0.f;
        if ((unsigned)gy < 128u && (unsigned)gx < 128u)
            v = xb[ic * HW + gy * 128 + gx];
        s_in[idx] = v;
    }
    for (int idx = tid; idx < NO * 144; idx += 64) s_wf[idx] = g_wf[j * 2592 + idx];
    for (int idx = tid; idx < NO * 48;  idx += 64) s_w1[idx] = g_w1[j * 864 + idx];
    __syncthreads();

    const int r  = tid >> 2;
    const int c0 = (tid & 3) * 4;

    float acc[NO][4];
#pragma unroll
    for (int o = 0; o < NO; o++) {
        float bb = (NO == 9) ? mask_b[o] : off_b[hj * 18 + o];
#pragma unroll
        for (int p = 0; p < 4; p++) acc[o][p] = bb;
    }

    // 3x3 folded part
#pragma unroll 1
    for (int ic = 0; ic < 16; ic++) {
        float v[3][6];
        const float* sp = s_in + ic * 324 + r * 18 + c0;
#pragma unroll
        for (int dy = 0; dy < 3; dy++)
#pragma unroll
            for (int dx = 0; dx < 6; dx++)
                v[dy][dx] = sp[dy * 18 + dx];

        const float* wp = s_wf + ic * 9;
#pragma unroll
        for (int o = 0; o < NO; o++) {
#pragma unroll
            for (int t = 0; t < 9; t++) {
                float wv = wp[o * 144 + t];
                int dy = t / 3, dx = t % 3;
#pragma unroll
                for (int p = 0; p < 4; p++)
                    acc[o][p] = fmaf(wv, v[dy][dx + p], acc[o][p]);
            }
        }
    }

    // 1x1 remainder over x[16:64]
    const int pxb = (h0 + r) * 128 + w0 + c0;
    const float* xr = xb + 16 * HW + pxb;
#pragma unroll 4
    for (int c = 0; c < 48; c++) {
        float4 xv = *reinterpret_cast<const float4*>(xr + (size_t)c * HW);
#pragma unroll
        for (int o = 0; o < NO; o++) {
            float wv = s_w1[o * 48 + c];
            acc[o][0] = fmaf(wv, xv.x, acc[o][0]);
            acc[o][1] = fmaf(wv, xv.y, acc[o][1]);
            acc[o][2] = fmaf(wv, xv.z, acc[o][2]);
            acc[o][3] = fmaf(wv, xv.w, acc[o][3]);
        }
    }

    if (NO == 9) {
        float* mp = g_mask + (size_t)b * 9 * HW + pxb;
#pragma unroll
        for (int o = 0; o < 9; o++) {
            float4 s;
            s.x = 1.f / (1.f + __expf(-acc[o][0]));
            s.y = 1.f / (1.f + __expf(-acc[o][1]));
            s.z = 1.f / (1.f + __expf(-acc[o][2]));
            s.w = 1.f / (1.f + __expf(-acc[o][3]));
            *reinterpret_cast<float4*>(mp + (size_t)o * HW) = s;
        }
    } else {
        const int slice = b * 4 + hj;
        float* op = g_off + ((size_t)slice * 9) * HW * 2 + (size_t)pxb * 2;
#pragma unroll
        for (int k = 0; k < 9; k++) {
            float4 a = make_float4(acc[2 * k][0], acc[2 * k + 1][0],
                                   acc[2 * k][1], acc[2 * k + 1][1]);
            float4 bq = make_float4(acc[2 * k][2], acc[2 * k + 1][2],
                                    acc[2 * k][3], acc[2 * k + 1][3]);
            float* kp = op + (size_t)k * HW * 2;
            *reinterpret_cast<float4*>(kp)     = a;
            *reinterpret_cast<float4*>(kp + 4) = bq;
        }
    }
}

// ---------------------------------------------------------------------------
// Sampler: thread = (b, g, channel-group of 4, h, pixel-pair).
// 524288 threads.  Corner indices/weights computed in registers per tap,
// reused over 4 channels x 2 images.
// ---------------------------------------------------------------------------
__global__ __launch_bounds__(256) void sample_kernel(
    const float* __restrict__ y, float* __restrict__ out)
{
    int idx = blockIdx.x * 256 + threadIdx.x;
    const int w2 = idx & 63;  idx >>= 6;
    const int h  = idx & 127; idx >>= 7;
    const int cg = idx & 3;   idx >>= 2;
    const int g  = idx & 3;
    const int b  = idx >> 2;
    const int w  = w2 * 2;
    const int px = h * 128 + w;

    const float* off = g_off + ((size_t)(b * 4 + g) * 9) * HW * 2;
    const float* msk = g_mask + (size_t)b * 9 * HW;
    const float* y1  = y + (size_t)(b * 64 + g * 16 + cg * 4) * HW;
    const float* y2  = y + (size_t)((b + 4) * 64 + g * 16 + cg * 4) * HW;
    float* o1 = out + ((size_t)(b * 64 + g * 16 + cg * 4) * 9) * HW + px;
    float* o2 = out + ((size_t)((b + 4) * 64 + g * 16 + cg * 4) * 9) * HW + px;

    const int dil = 2 * g + 1;

#pragma unroll 1
    for (int k = 0; k < 9; k++) {
        const int ky = k / 3 - 1;
        const int kx = k % 3 - 1;
        const float basey = (float)(h + ky * dil);
        const float basex = (float)(w + kx * dil);

        const float4 o4 = *reinterpret_cast<const float4*>(off + ((size_t)k * HW + px) * 2);
        const float2 m2 = *reinterpret_cast<const float2*>(msk + (size_t)k * HW + px);

        int   ci[2][4];
        float cw[2][4];
#pragma unroll
        for (int p = 0; p < 2; p++) {
            float py  = basey + (p ? o4.z : o4.x);
            float pxx = basex + (float)p + (p ? o4.w : o4.y);
            float m   = p ? m2.y : m2.x;

            float fy0 = floorf(py);
            float fx0 = floorf(pxx);
            float wy = py - fy0;
            float wx = pxx - fx0;

            bool vy0 = (fy0 >= 0.f)  && (fy0 <= 127.f);
            bool vy1 = (fy0 >= -1.f) && (fy0 <= 126.f);
            bool vx0 = (fx0 >= 0.f)  && (fx0 <= 127.f);
            bool vx1 = (fx0 >= -1.f) && (fx0 <= 126.f);

            int y0c = (int)fminf(fmaxf(fy0,       0.f), 127.f);
            int y1c = (int)fminf(fmaxf(fy0 + 1.f, 0.f), 127.f);
            int x0c = (int)fminf(fmaxf(fx0,       0.f), 127.f);
            int x1c = (int)fminf(fmaxf(fx0 + 1.f, 0.f), 127.f);

            float w00 = (1.f - wy) * (1.f - wx) * m; if (!(vy0 && vx0)) w00 = 0.f;
            float w01 = (1.f - wy) * wx        * m; if (!(vy0 && vx1)) w01 = 0.f;
            float w10 = wy        * (1.f - wx) * m; if (!(vy1 && vx0)) w10 = 0.f;
            float w11 = wy        * wx         * m; if (!(vy1 && vx1)) w11 = 0.f;

            ci[p][0] = y0c * 128 + x0c;  cw[p][0] = w00;
            ci[p][1] = y0c * 128 + x1c;  cw[p][1] = w01;
            ci[p][2] = y1c * 128 + x0c;  cw[p][2] = w10;
            ci[p][3] = y1c * 128 + x1c;  cw[p][3] = w11;
        }

#pragma unroll
        for (int c = 0; c < 4; c++) {
            const float* s1 = y1 + (size_t)c * HW;
            const float* s2 = y2 + (size_t)c * HW;

            float r1x = cw[0][0] * s1[ci[0][0]] + cw[0][1] * s1[ci[0][1]]
                      + cw[0][2] * s1[ci[0][2]] + cw[0][3] * s1[ci[0][3]];
            float r1y = cw[1][0] * s1[ci[1][0]] + cw[1][1] * s1[ci[1][1]]
                      + cw[1][2] * s1[ci[1][2]] + cw[1][3] * s1[ci[1][3]];
            float r2x = cw[0][0] * s2[ci[0][0]] + cw[0][1] * s2[ci[0][1]]
                      + cw[0][2] * s2[ci[0][2]] + cw[0][3] * s2[ci[0][3]];
            float r2y = cw[1][0] * s2[ci[1][0]] + cw[1][1] * s2[ci[1][1]]
                      + cw[1][2] * s2[ci[1][2]] + cw[1][3] * s2[ci[1][3]];

            *reinterpret_cast<float2*>(o1 + (size_t)(c * 9 + k) * HW) = make_float2(r1x, r1y);
            *reinterpret_cast<float2*>(o2 + (size_t)(c * 9 + k) * HW) = make_float2(r2x, r2y);
        }
    }
}

// ---------------------------------------------------------------------------
extern "C" void kernel_launch(void* const* d_in, const int* in_sizes, int n_in,
                              void* d_out, int out_size)
{
    const float *x = nullptr, *y = nullptr, *off_pw = nullptr, *off_w = nullptr,
                *off_b = nullptr, *mask_pw = nullptr, *mask_w = nullptr, *mask_b = nullptr;
    for (int i = 0; i < n_in; i++) {
        switch (in_sizes[i]) {
            case 4194304: x       = (const float*)d_in[i]; break;
            case 8388608: y       = (const float*)d_in[i]; break;
            case 9216:    off_pw  = (const float*)d_in[i]; break;
            case 4608:    off_w   = (const float*)d_in[i]; break;
            case 72:      off_b   = (const float*)d_in[i]; break;
            case 2304:    mask_pw = (const float*)d_in[i]; break;
            case 576:     mask_w  = (const float*)d_in[i]; break;
            case 9:       mask_b  = (const float*)d_in[i]; break;
            default: break;
        }
    }
    float* out = (float*)d_out;

    fold_kernel<<<56, 256>>>(mask_pw, mask_w, off_pw, off_w);
    fused_head_kernel<18><<<dim3(8, 8, NB * 4), 64>>>(x, mask_b, off_b);
    fused_head_kernel<9 ><<<dim3(8, 8, NB),     64>>>(x, mask_b, off_b);
    sample_kernel<<<2048, 256>>>(y, out);
}

// round 7
// speedup vs baseline: 1.3957x; 1.0449x over previous
#include <cuda_runtime.h>
#include <cstdint>

#define HW 16384          // 128*128
#define NB 4
#define NG 4
#define K2 9

typedef unsigned long long ull;

#define FMA2(d, a, b, c) \
    asm("fma.rn.f32x2 %0, %1, %2, %3;" : "=l"(d) : "l"(a), "l"(b), "l"(c))
#define PACKF(dst, lo, hi) \
    asm("mov.b64 %0, {%1, %2};" : "=l"(dst) : "r"(__float_as_uint(lo)), "r"(__float_as_uint(hi)))
#define UNPACKF(lo, hi, src) \
    asm("mov.b64 {%0, %1}, %2;" : "=r"(lo), "=r"(hi) : "l"(src))

// Scratch (allocation-free __device__ globals)
__device__ __align__(16) float g_off[NB * NG * 18 * HW];     // [slice][o][px]  o=2k:dy 2k+1:dx
__device__ __align__(16) float g_mask[NB * K2 * HW];         // [b][k][px]
__device__ __align__(16) float2 g_wf2[5 * 16 * 18 * 9];      // folded 3x3 {w,w}: [j][ic][o][t]
__device__ __align__(16) float2 g_w12[5 * 48 * 18];          // 1x1 remainder {w,w}: [j][c][o]

// ---------------------------------------------------------------------------
// Fold: g_wf2[j][ic][o][t] = {s,s}, s = sum_c headW[j][o][c] * convW[j][c][ic][t]
//       g_w12[j][c][o]     = {headW[j][o][16+c]} x2
// ---------------------------------------------------------------------------
__global__ void fold_kernel(
    const float* __restrict__ mask_pw,  // (16,16,3,3)
    const float* __restrict__ mask_w,   // (9,64)
    const float* __restrict__ off_pw,   // (4,16,16,3,3)
    const float* __restrict__ off_w)    // (4,18,64)
{
    int idx = blockIdx.x * 256 + threadIdx.x;
    for (int e = idx; e < 5 * 16 * 18 * 9; e += gridDim.x * 256) {
        int j  = e / 2592;
        int r  = e - j * 2592;
        int ic = r / 162;
        int r2 = r - ic * 162;
        int o  = r2 / 9;
        int t  = r2 - o * 9;
        float s = 0.f;
        if (!(j == 0 && o >= 9)) {
            const float* hw = (j == 0) ? (mask_w + o * 64)
                                       : (off_w + ((j - 1) * 18 + o) * 64);
            const float* cw = (j == 0) ? mask_pw : (off_pw + (j - 1) * 2304);
#pragma unroll
            for (int c = 0; c < 16; c++)
                s = fmaf(hw[c], cw[c * 144 + ic * 9 + t], s);
        }
        g_wf2[e] = make_float2(s, s);
    }
    for (int e = idx; e < 5 * 48 * 18; e += gridDim.x * 256) {
        int j = e / (48 * 18);
        int r = e - j * 48 * 18;
        int c = r / 18;
        int o = r - c * 18;
        float s = 0.f;
        if (!(j == 0 && o >= 9)) {
            const float* hw = (j == 0) ? (mask_w + o * 64)
                                       : (off_w + ((j - 1) * 18 + o) * 64);
            s = hw[16 + c];
        }
        g_w12[e] = make_float2(s, s);
    }
}

// ---------------------------------------------------------------------------
// Fused head: (3x3 conv 16->NO folded) + (1x1 48->NO) + bias, f32x2 packed.
// grid (4, 8, NB*5): tile h=16, w=32.  block 128 = 2 output-halves x 64 px-grps.
// Thread: 8 px (4 f32x2 pairs) x 9 outputs.  j=0: mask+sigmoid, j>=1: offsets.
// Dynamic smem: s_in[16][18][34] | s_wf2[16][18][9] | s_w12[48][18]
// ---------------------------------------------------------------------------
__global__ __launch_bounds__(128) void fused_head_kernel(
    const float* __restrict__ x,
    const float* __restrict__ mask_b,   // (9,)
    const float* __restrict__ off_b)    // (4,18)
{
    extern __shared__ float smem[];
    float*  s_in  = smem;                          // 16*18*34 = 9792 floats
    float2* s_wf2 = (float2*)(smem + 9792);        // 2592 float2
    float2* s_w12 = s_wf2 + 2592;                  // 864 float2

    const int bz = blockIdx.z;
    const int j  = bz % 5;        // 0 = mask head, 1..4 = offset head g=j-1
    const int b  = bz / 5;
    const int h0 = blockIdx.y * 16;
    const int w0 = blockIdx.x * 32;
    const int tid = threadIdx.x;

    const float* xb = x + (size_t)b * 64 * HW;
    for (int idx = tid; idx < 9792; idx += 128) {
        int ic  = idx / 612;
        int rem = idx - ic * 612;
        int ly  = rem / 34;
        int lx  = rem - ly * 34;
        int gy = h0 - 1 + ly;
        int gx = w0 - 1 + lx;
        float v = 0.f;
        if ((unsigned)gy < 128u && (unsigned)gx < 128u)
            v = xb[ic * HW + gy * 128 + gx];
        s_in[idx] = v;
    }
    {
        const float2* src = g_wf2 + j * 2592;
        for (int idx = tid; idx < 2592; idx += 128) s_wf2[idx] = src[idx];
        const float2* src2 = g_w12 + j * 864;
        for (int idx = tid; idx < 864; idx += 128) s_w12[idx] = src2[idx];
    }
    __syncthreads();

    const int oh  = tid >> 6;        // output half: o_global = oh*9 + o
    const int grp = tid & 63;
    const int r   = grp >> 2;        // row 0..15
    const int c0  = (grp & 3) * 8;   // col base 0,8,16,24

    if (j == 0 && oh == 1) return;   // mask head has only 9 outputs

    ull acc2[9][4];
#pragma unroll
    for (int o = 0; o < 9; o++) {
        float bb = (j == 0) ? mask_b[o] : off_b[(j - 1) * 18 + oh * 9 + o];
        ull bv; PACKF(bv, bb, bb);
#pragma unroll
        for (int q = 0; q < 4; q++) acc2[o][q] = bv;
    }

    // 3x3 folded part
#pragma unroll 1
    for (int ic = 0; ic < 16; ic++) {
        const float* rb = s_in + ic * 612 + r * 34 + c0;
        const float2* wb = s_wf2 + (ic * 18 + oh * 9) * 9;
#pragma unroll
        for (int dy = 0; dy < 3; dy++) {
            float v[10];
            const float* rp = rb + dy * 34;
#pragma unroll
            for (int i = 0; i < 10; i++) v[i] = rp[i];
            ull vp[9];
#pragma unroll
            for (int i = 0; i < 9; i++) PACKF(vp[i], v[i], v[i + 1]);
#pragma unroll
            for (int o = 0; o < 9; o++) {
#pragma unroll
                for (int dx = 0; dx < 3; dx++) {
                    ull w2 = *(const ull*)&wb[o * 9 + dy * 3 + dx];
                    FMA2(acc2[o][0], w2, vp[dx + 0], acc2[o][0]);
                    FMA2(acc2[o][1], w2, vp[dx + 2], acc2[o][1]);
                    FMA2(acc2[o][2], w2, vp[dx + 4], acc2[o][2]);
                    FMA2(acc2[o][3], w2, vp[dx + 6], acc2[o][3]);
                }
            }
        }
    }

    // 1x1 remainder over x[16:64]
    const int pxb = (h0 + r) * 128 + w0 + c0;
    const float* xr = xb + 16 * HW + pxb;
#pragma unroll 2
    for (int c = 0; c < 48; c++) {
        ulonglong2 u01 = *(const ulonglong2*)(xr + (size_t)c * HW);
        ulonglong2 u23 = *(const ulonglong2*)(xr + (size_t)c * HW + 4);
        const float2* wp = s_w12 + c * 18 + oh * 9;
#pragma unroll
        for (int o = 0; o < 9; o++) {
            ull w2 = *(const ull*)&wp[o];
            FMA2(acc2[o][0], w2, u01.x, acc2[o][0]);
            FMA2(acc2[o][1], w2, u01.y, acc2[o][1]);
            FMA2(acc2[o][2], w2, u23.x, acc2[o][2]);
            FMA2(acc2[o][3], w2, u23.y, acc2[o][3]);
        }
    }

    if (j == 0) {
        float* mp = g_mask + (size_t)b * 9 * HW + pxb;
#pragma unroll
        for (int o = 0; o < 9; o++) {
            float f[8];
#pragma unroll
            for (int q = 0; q < 4; q++) {
                unsigned lo, hi; UNPACKF(lo, hi, acc2[o][q]);
                f[2 * q]     = 1.f / (1.f + __expf(-__uint_as_float(lo)));
                f[2 * q + 1] = 1.f / (1.f + __expf(-__uint_as_float(hi)));
            }
            float* dst = mp + (size_t)o * HW;
            *reinterpret_cast<float4*>(dst)     = make_float4(f[0], f[1], f[2], f[3]);
            *reinterpret_cast<float4*>(dst + 4) = make_float4(f[4], f[5], f[6], f[7]);
        }
    } else {
        const int slice = b * 4 + (j - 1);
        float* op = g_off + ((size_t)slice * 18 + oh * 9) * HW + pxb;
#pragma unroll
        for (int o = 0; o < 9; o++) {
            float* dst = op + (size_t)o * HW;
            ulonglong2 s0; s0.x = acc2[o][0]; s0.y = acc2[o][1];
            ulonglong2 s1; s1.x = acc2[o][2]; s1.y = acc2[o][3];
            *reinterpret_cast<ulonglong2*>(dst)     = s0;
            *reinterpret_cast<ulonglong2*>(dst + 4) = s1;
        }
    }
}

// ---------------------------------------------------------------------------
// Sampler: thread = (b, g, channel-group of 4, h, pixel-pair).  524288 threads.
// Corner indices/weights in registers per tap, reused over 4 ch x 2 images.
// ---------------------------------------------------------------------------
__global__ __launch_bounds__(256) void sample_kernel(
    const float* __restrict__ y, float* __restrict__ out)
{
    int idx = blockIdx.x * 256 + threadIdx.x;
    const int w2 = idx & 63;  idx >>= 6;
    const int h  = idx & 127; idx >>= 7;
    const int cg = idx & 3;   idx >>= 2;
    const int g  = idx & 3;
    const int b  = idx >> 2;
    const int w  = w2 * 2;
    const int px = h * 128 + w;

    const float* off = g_off + (size_t)(b * 4 + g) * 18 * HW;
    const float* msk = g_mask + (size_t)b * 9 * HW;
    const float* y1  = y + (size_t)(b * 64 + g * 16 + cg * 4) * HW;
    const float* y2  = y + (size_t)((b + 4) * 64 + g * 16 + cg * 4) * HW;
    float* o1 = out + ((size_t)(b * 64 + g * 16 + cg * 4) * 9) * HW + px;
    float* o2 = out + ((size_t)((b + 4) * 64 + g * 16 + cg * 4) * 9) * HW + px;

    const int dil = 2 * g + 1;

#pragma unroll 1
    for (int k = 0; k < 9; k++) {
        const int ky = k / 3 - 1;
        const int kx = k % 3 - 1;
        const float basey = (float)(h + ky * dil);
        const float basex = (float)(w + kx * dil);

        const float2 dy2 = *reinterpret_cast<const float2*>(off + (size_t)(2 * k) * HW + px);
        const float2 dx2 = *reinterpret_cast<const float2*>(off + (size_t)(2 * k + 1) * HW + px);
        const float2 m2  = *reinterpret_cast<const float2*>(msk + (size_t)k * HW + px);

        int   ci[2][4];
        float cw[2][4];
#pragma unroll
        for (int p = 0; p < 2; p++) {
            float py  = basey + (p ? dy2.y : dy2.x);
            float pxx = basex + (float)p + (p ? dx2.y : dx2.x);
            float m   = p ? m2.y : m2.x;

            float fy0 = floorf(py);
            float fx0 = floorf(pxx);
            float wy = py - fy0;
            float wx = pxx - fx0;

            bool vy0 = (fy0 >= 0.f)  && (fy0 <= 127.f);
            bool vy1 = (fy0 >= -1.f) && (fy0 <= 126.f);
            bool vx0 = (fx0 >= 0.f)  && (fx0 <= 127.f);
            bool vx1 = (fx0 >= -1.f) && (fx0 <= 126.f);

            int y0c = (int)fminf(fmaxf(fy0,       0.f), 127.f);
            int y1c = (int)fminf(fmaxf(fy0 + 1.f, 0.f), 127.f);
            int x0c = (int)fminf(fmaxf(fx0,       0.f), 127.f);
            int x1c = (int)fminf(fmaxf(fx0 + 1.f, 0.f), 127.f);

            float w00 = (1.f - wy) * (1.f - wx) * m; if (!(vy0 && vx0)) w00 = 0.f;
            float w01 = (1.f - wy) * wx        * m; if (!(vy0 && vx1)) w01 = 0.f;
            float w10 = wy        * (1.f - wx) * m; if (!(vy1 && vx0)) w10 = 0.f;
            float w11 = wy        * wx         * m; if (!(vy1 && vx1)) w11 = 0.f;

            ci[p][0] = y0c * 128 + x0c;  cw[p][0] = w00;
            ci[p][1] = y0c * 128 + x1c;  cw[p][1] = w01;
            ci[p][2] = y1c * 128 + x0c;  cw[p][2] = w10;
            ci[p][3] = y1c * 128 + x1c;  cw[p][3] = w11;
        }

#pragma unroll
        for (int c = 0; c < 4; c++) {
            const float* s1 = y1 + (size_t)c * HW;
            const float* s2 = y2 + (size_t)c * HW;

            float r1x = cw[0][0] * s1[ci[0][0]] + cw[0][1] * s1[ci[0][1]]
                      + cw[0][2] * s1[ci[0][2]] + cw[0][3] * s1[ci[0][3]];
            float r1y = cw[1][0] * s1[ci[1][0]] + cw[1][1] * s1[ci[1][1]]
                      + cw[1][2] * s1[ci[1][2]] + cw[1][3] * s1[ci[1][3]];
            float r2x = cw[0][0] * s2[ci[0][0]] + cw[0][1] * s2[ci[0][1]]
                      + cw[0][2] * s2[ci[0][2]] + cw[0][3] * s2[ci[0][3]];
            float r2y = cw[1][0] * s2[ci[1][0]] + cw[1][1] * s2[ci[1][1]]
                      + cw[1][2] * s2[ci[1][2]] + cw[1][3] * s2[ci[1][3]];

            *reinterpret_cast<float2*>(o1 + (size_t)(c * 9 + k) * HW) = make_float2(r1x, r1y);
            *reinterpret_cast<float2*>(o2 + (size_t)(c * 9 + k) * HW) = make_float2(r2x, r2y);
        }
    }
}

// ---------------------------------------------------------------------------
extern "C" void kernel_launch(void* const* d_in, const int* in_sizes, int n_in,
                              void* d_out, int out_size)
{
    const float *x = nullptr, *y = nullptr, *off_pw = nullptr, *off_w = nullptr,
                *off_b = nullptr, *mask_pw = nullptr, *mask_w = nullptr, *mask_b = nullptr;
    for (int i = 0; i < n_in; i++) {
        switch (in_sizes[i]) {
            case 4194304: x       = (const float*)d_in[i]; break;
            case 8388608: y       = (const float*)d_in[i]; break;
            case 9216:    off_pw  = (const float*)d_in[i]; break;
            case 4608:    off_w   = (const float*)d_in[i]; break;
            case 72:      off_b   = (const float*)d_in[i]; break;
            case 2304:    mask_pw = (const float*)d_in[i]; break;
            case 576:     mask_w  = (const float*)d_in[i]; break;
            case 9:       mask_b  = (const float*)d_in[i]; break;
            default: break;
        }
    }
    float* out = (float*)d_out;

    const int head_smem = (9792 + 2 * 2592 + 2 * 864) * 4;   // 66816 bytes
    cudaFuncSetAttribute(fused_head_kernel,
                         cudaFuncAttributeMaxDynamicSharedMemorySize, head_smem);

    fold_kernel<<<56, 256>>>(mask_pw, mask_w, off_pw, off_w);
    fused_head_kernel<<<dim3(4, 8, NB * 5), 128, head_smem>>>(x, mask_b, off_b);
    sample_kernel<<<2048, 256>>>(y, out);
}